// round 13
// baseline (speedup 1.0000x reference)
#include <cuda_runtime.h>
#include <cuda_fp16.h>
#include <cstdint>

// Conv2d 3x3 VALID, C_in=C_out=8, 2048x2048 fp32 -> (8, 2046, 2046)
// Round 13: R12 (pure-fp16 mma, kx folded into K, double-buffered frags)
// + smem-transposed epilogue: accumulators staged per-warp in smem, then
// stored as coalesced 64B float2 runs (STG wavefronts 8x fewer).

#define CIN   8
#define IH    2048
#define IW    2048
#define OHH   2046
#define OWW   2046
#define CH    (IH*IW)
#define TPX   128
#define NW    4
#define RPW   2
#define TR    (NW*RPW)      // 8 output rows per block
#define INR   (TR+2)        // 10 staged input rows
#define INPX  (TPX+2)       // 130
#define WPP   4             // u32 words per staged pixel
#define ROWSTRIDE (INPX*WPP)
#define NTHREADS  (NW*32)
#define NCHUNK (TPX/16)     // 8
#define NITEM  (INR*(INPX/2))
#define GS    36            // obuf group stride (bank-conflict-free)

typedef uint32_t u32;

__device__ __forceinline__ u32 f16x2_pack(float hv, float lv) {
    u32 r;
    asm("cvt.rn.f16x2.f32 %0, %1, %2;" : "=r"(r) : "f"(hv), "f"(lv));
    return r;
}

__device__ __forceinline__ void mma16(float* d,
                                      u32 a0, u32 a1, u32 a2, u32 a3,
                                      u32 b0, u32 b1) {
    asm volatile(
        "mma.sync.aligned.m16n8k16.row.col.f32.f16.f16.f32 "
        "{%0,%1,%2,%3}, {%4,%5,%6,%7}, {%8,%9}, {%0,%1,%2,%3};"
        : "+f"(d[0]), "+f"(d[1]), "+f"(d[2]), "+f"(d[3])
        : "r"(a0), "r"(a1), "r"(a2), "r"(a3), "r"(b0), "r"(b1));
}

__device__ __forceinline__ void mma8(float* d, u32 a0, u32 a1, u32 b0) {
    asm volatile(
        "mma.sync.aligned.m16n8k8.row.col.f32.f16.f16.f32 "
        "{%0,%1,%2,%3}, {%4,%5}, {%6}, {%0,%1,%2,%3};"
        : "+f"(d[0]), "+f"(d[1]), "+f"(d[2]), "+f"(d[3])
        : "r"(a0), "r"(a1), "r"(b0));
}

__global__ __launch_bounds__(NTHREADS)
void conv3x3_mma_kernel(const float* __restrict__ x,
                        const float* __restrict__ w,
                        float* __restrict__ out) {
    __shared__ u32 stage[INR * ROWSTRIDE];
    // per-warp output transpose buffer: [group = row*8+cout][32 px + pad]
    __shared__ __align__(16) float obuf[NW][16][GS];

    const int tid  = threadIdx.x;
    const int wid  = tid >> 5;
    const int lane = tid & 31;
    const int gid  = lane >> 2;   // 0..7 : M row (pixel) selector
    const int q    = lane & 3;    // 0..3 : k-pair / cout-pair selector

    int x0 = blockIdx.x * TPX; if (x0 > OWW - TPX) x0 = OWW - TPX;
    int y0 = blockIdx.y * TR;  if (y0 > OHH - TR)  y0 = OHH - TR;

    // ---- weight regs: wb[t] = f16x2(w[gid][2q+1][t] hi, w[gid][2q][t] lo) ----
    u32 wb[9];
    #pragma unroll
    for (int t = 0; t < 9; ++t) {
        int ky = t / 3, kx = t % 3;
        float w0v = __ldg(&w[((gid * CIN + 2 * q)     * 3 + ky) * 3 + kx]);
        float w1v = __ldg(&w[((gid * CIN + 2 * q + 1) * 3 + ky) * 3 + kx]);
        wb[t] = f16x2_pack(w1v, w0v);
    }

    // ---- stage inputs (unrolled for LDG MLP) ----
    #pragma unroll
    for (int k = 0; k < (NITEM + NTHREADS - 1) / NTHREADS; ++k) {
        int it = tid + k * NTHREADS;
        if (it < NITEM) {
            int b  = it / (INPX / 2);
            int xl = (it - b * (INPX / 2)) * 2;
            const float* ip = x + (size_t)(y0 + b) * IW + (x0 + xl);
            float2 v[8];
            #pragma unroll
            for (int c = 0; c < 8; ++c)
                v[c] = *reinterpret_cast<const float2*>(ip + (size_t)c * CH);
            u32 w0[4], w1[4];
            #pragma unroll
            for (int j = 0; j < 4; ++j) {
                w0[j] = f16x2_pack(v[2*j+1].x, v[2*j].x);
                w1[j] = f16x2_pack(v[2*j+1].y, v[2*j].y);
            }
            u32* dst = &stage[(size_t)b * ROWSTRIDE + (size_t)xl * WPP];
            reinterpret_cast<uint4*>(dst)[0] = make_uint4(w0[0], w0[1], w0[2], w0[3]);
            reinterpret_cast<uint4*>(dst)[1] = make_uint4(w1[0], w1[1], w1[2], w1[3]);
        }
    }
    __syncthreads();

    const size_t PL = (size_t)OHH * OWW;
    const int r0 = y0 + RPW * wid;

    const u32* rbase[RPW + 2];
    #pragma unroll
    for (int ir = 0; ir < RPW + 2; ++ir)
        rbase[ir] = &stage[(size_t)(RPW * wid + ir) * ROWSTRIDE + (size_t)gid * WPP + q];

    u32 L[2][4][3], H[2][4][3];
    #pragma unroll
    for (int ir = 0; ir < 4; ++ir) {
        const u32* rp = rbase[ir];
        #pragma unroll
        for (int kx = 0; kx < 3; ++kx) {
            L[0][ir][kx] = rp[kx * WPP];
            H[0][ir][kx] = rp[(kx + 8) * WPP];
        }
    }

    float* ob = &obuf[wid][0][0];

    #pragma unroll
    for (int chunk = 0; chunk < NCHUNK; ++chunk) {
        const int cur = chunk & 1, nxt = cur ^ 1;

        if (chunk + 1 < NCHUNK) {
            const int co = (chunk + 1) * 16 * WPP;
            #pragma unroll
            for (int ir = 0; ir < 4; ++ir) {
                const u32* rp = rbase[ir] + co;
                #pragma unroll
                for (int kx = 0; kx < 3; ++kx) {
                    L[nxt][ir][kx] = rp[kx * WPP];
                    H[nxt][ir][kx] = rp[(kx + 8) * WPP];
                }
            }
        }

        float a0[4] = {0,0,0,0};
        float a1[4] = {0,0,0,0};
        #define Lc L[cur]
        #define Hc H[cur]
        mma16(a0, Lc[0][0],Hc[0][0], Lc[0][1],Hc[0][1], wb[0], wb[1]);
        mma16(a1, Lc[1][0],Hc[1][0], Lc[1][1],Hc[1][1], wb[0], wb[1]);
        mma16(a0, Lc[0][2],Hc[0][2], Lc[1][0],Hc[1][0], wb[2], wb[3]);
        mma16(a1, Lc[1][2],Hc[1][2], Lc[2][0],Hc[2][0], wb[2], wb[3]);
        mma16(a0, Lc[1][1],Hc[1][1], Lc[1][2],Hc[1][2], wb[4], wb[5]);
        mma16(a1, Lc[2][1],Hc[2][1], Lc[2][2],Hc[2][2], wb[4], wb[5]);
        mma16(a0, Lc[2][0],Hc[2][0], Lc[2][1],Hc[2][1], wb[6], wb[7]);
        mma16(a1, Lc[3][0],Hc[3][0], Lc[3][1],Hc[3][1], wb[6], wb[7]);
        mma8 (a0, Lc[2][2],Hc[2][2], wb[8]);
        mma8 (a1, Lc[3][2],Hc[3][2], wb[8]);
        #undef Lc
        #undef Hc

        // ---- STS accumulators into per-warp transpose buffer ----
        // group = row*8 + cout; word = group*GS + px(0..31)
        {
            const int c16 = cur * 16;
            int i0 = (2 * q) * GS + c16 + gid;        // row0, cout 2q
            int i1 = i0 + GS;                          // row0, cout 2q+1
            ob[i0]     = a0[0];  ob[i1]     = a0[1];
            ob[i0 + 8] = a0[2];  ob[i1 + 8] = a0[3];
            ob[i0 + 8*GS]     = a1[0];  ob[i1 + 8*GS]     = a1[1];
            ob[i0 + 8*GS + 8] = a1[2];  ob[i1 + 8*GS + 8] = a1[3];
        }

        // ---- flush every 2 chunks with coalesced float2 stores ----
        if (cur) {
            __syncwarp();
            const int pb = x0 + (chunk - 1) * 16;   // 32-px group base
            #pragma unroll
            for (int rnd = 0; rnd < 8; ++rnd) {
                int g = (lane >> 3) * 4 + (rnd & 3);   // 0..15
                int j = (lane & 7) + ((rnd >> 2) << 3); // 0..15
                int row  = g >> 3;
                int cout = g & 7;
                float2 v = *reinterpret_cast<const float2*>(&obuf[wid][g][j * 2]);
                float* op = out + (size_t)cout * PL + (size_t)(r0 + row) * OWW
                            + (pb + j * 2);
                *reinterpret_cast<float2*>(op) = v;
            }
            __syncwarp();
        }
    }
}

extern "C" void kernel_launch(void* const* d_in, const int* in_sizes, int n_in,
                              void* d_out, int out_size) {
    const float* x = (const float*)d_in[0];   // (8, 2048, 2048) fp32
    const float* w = (const float*)d_in[1];   // (8, 8, 3, 3) fp32
    float* out = (float*)d_out;               // (8, 2046, 2046) fp32

    dim3 grid((OWW + TPX - 1) / TPX,          // 16
              (OHH + TR - 1) / TR);           // 256
    conv3x3_mma_kernel<<<grid, NTHREADS>>>(x, w, out);
}